// round 5
// baseline (speedup 1.0000x reference)
#include <cuda_runtime.h>
#include <cuda_fp16.h>
#include <cstdint>

#define D_IN   768
#define D_SAE  12288
#define T_LEN  64
#define KTOP   64
#define BATCH  32
#define NROWS  (BATCH * T_LEN)   // 2048

// ---------------- scratch (static device globals; no allocations) ----------------
__device__ __align__(16) float  g_pre[(size_t)NROWS * D_SAE];   // 96 MB approx pre
__device__ __align__(16) float  g_WT [(size_t)D_SAE * D_IN];    // W_enc^T fp32 (exact dots)
__device__ __align__(16) __half g_Ah [(size_t)NROWS * D_IN];    // x fp16
__device__ __align__(16) __half g_Bh [(size_t)D_SAE * D_IN];    // W_enc^T fp16 [n][k]
__device__ int   g_topidx[NROWS * 128];
__device__ float g_topval[NROWS * 128];
__device__ int   g_zidx[NROWS * KTOP];
__device__ float g_zval[NROWS * KTOP];
__device__ float g_rowloss[NROWS];

// ---------------- helpers ----------------
__device__ __forceinline__ unsigned int fkey(float v) {
    unsigned int u = __float_as_uint(v);
    return (u & 0x80000000u) ? ~u : (u | 0x80000000u);
}
__device__ __forceinline__ float keyToFloat(unsigned int k) {
    unsigned int u = (k & 0x80000000u) ? (k & 0x7FFFFFFFu) : ~k;
    return __uint_as_float(u);
}
__device__ __forceinline__ unsigned long long makeComp(float v, int idx) {
    return ((unsigned long long)fkey(v) << 32) | (unsigned long long)(0xFFFFFFFFu - (unsigned int)idx);
}
__device__ __forceinline__ uint32_t smem_u32(const void* p) {
    uint32_t a;
    asm("{ .reg .u64 t; cvta.to.shared.u64 t, %1; cvt.u32.u64 %0, t; }" : "=r"(a) : "l"(p));
    return a;
}
__device__ __forceinline__ void cp16(uint32_t dst, const void* src) {
    asm volatile("cp.async.cg.shared.global [%0], [%1], 16;" :: "r"(dst), "l"(src));
}
#define CP_COMMIT() asm volatile("cp.async.commit_group;" ::: "memory")

__device__ __forceinline__ void ldm_x4(uint32_t& r0, uint32_t& r1, uint32_t& r2, uint32_t& r3,
                                       uint32_t addr) {
    asm volatile("ldmatrix.sync.aligned.m8n8.x4.shared.b16 {%0,%1,%2,%3}, [%4];"
                 : "=r"(r0), "=r"(r1), "=r"(r2), "=r"(r3) : "r"(addr));
}
__device__ __forceinline__ void mma16816(float* c, uint32_t a0, uint32_t a1, uint32_t a2,
                                         uint32_t a3, uint32_t b0, uint32_t b1) {
    asm volatile(
        "mma.sync.aligned.m16n8k16.row.col.f32.f16.f16.f32 "
        "{%0,%1,%2,%3}, {%4,%5,%6,%7}, {%8,%9}, {%0,%1,%2,%3};"
        : "+f"(c[0]), "+f"(c[1]), "+f"(c[2]), "+f"(c[3])
        : "r"(a0), "r"(a1), "r"(a2), "r"(a3), "r"(b0), "r"(b1));
}

// ======================================================================
// Conversions: x -> fp16, W_enc -> transposed fp32 + fp16
// ======================================================================
__global__ __launch_bounds__(256) void conv_A(const float* __restrict__ x) {
    const int i = blockIdx.x * 256 + threadIdx.x;
    g_Ah[i] = __float2half(x[i]);
}
__global__ __launch_bounds__(256) void conv_WT(const float* __restrict__ W) {
    __shared__ float s[32][65];
    const int nt = blockIdx.x;   // 192 tiles of 64 n
    const int kt = blockIdx.y;   // 24 tiles of 32 k
    const int tx = threadIdx.x & 63, ty = threadIdx.x >> 6;
#pragma unroll
    for (int r = 0; r < 8; ++r) {
        const int kl = ty + r * 4;
        s[kl][tx] = W[(size_t)(kt * 32 + kl) * D_SAE + nt * 64 + tx];
    }
    __syncthreads();
    const int nl = threadIdx.x >> 2, kq = (threadIdx.x & 3) * 8;
    const int n = nt * 64 + nl;
#pragma unroll
    for (int q = 0; q < 8; ++q) {
        const int kl = kq + q;
        const float v = s[kl][nl];
        g_WT[(size_t)n * D_IN + kt * 32 + kl] = v;
        g_Bh[(size_t)n * D_IN + kt * 32 + kl] = __float2half(v);
    }
}

// ======================================================================
// fp16 mma.sync GEMM: g_pre[2048,12288] = X @ W + b (approx, fp32 accum)
// CTA 128x128, BK=32, 3-stage cp.async, 8 warps (64x32 each).
// ======================================================================
#define GSMEM 61440   // 3 * (128*40 A + 128*40 B) halves * 2B

__global__ __launch_bounds__(256, 1) void gemm_mma(const float* __restrict__ bias) {
    extern __shared__ __align__(16) char dsm[];
    const uint32_t sb = smem_u32(dsm);
    const int tid = threadIdx.x, lane = tid & 31, w = tid >> 5;
    const int row0 = blockIdx.y * 128, col0 = blockIdx.x * 128;
    const int m_off = (w & 1) * 64, n_off = (w >> 1) * 32;

    float acc[4][4][4];
#pragma unroll
    for (int i = 0; i < 4; ++i)
#pragma unroll
        for (int j = 0; j < 4; ++j)
#pragma unroll
            for (int q = 0; q < 4; ++q) acc[i][j][q] = 0.f;

    // stage s: A at s*10240, B at 30720 + s*10240 (pitch 40 halves = 80B)
#define LOAD_STAGE(s, kt)                                                               \
    {                                                                                   \
        const int k0_ = (kt) * 32;                                                      \
        _Pragma("unroll")                                                               \
        for (int h_ = 0; h_ < 2; ++h_) {                                                \
            const int u_ = tid + h_ * 256;                                              \
            const int r_ = u_ >> 2, c_ = (u_ & 3) * 8;                                  \
            cp16(sb + (uint32_t)(s) * 10240u + (uint32_t)(r_ * 40 + c_) * 2u,           \
                 g_Ah + (size_t)(row0 + r_) * D_IN + k0_ + c_);                         \
            cp16(sb + 30720u + (uint32_t)(s) * 10240u + (uint32_t)(r_ * 40 + c_) * 2u,  \
                 g_Bh + (size_t)(col0 + r_) * D_IN + k0_ + c_);                         \
        }                                                                               \
        CP_COMMIT();                                                                    \
    }

    LOAD_STAGE(0, 0)
    LOAD_STAGE(1, 1)

    for (int kt = 0; kt < 24; ++kt) {
        asm volatile("cp.async.wait_group 1;" ::: "memory");
        __syncthreads();
        const int s = kt % 3;
        const uint32_t aBase = sb + (uint32_t)s * 10240u;
        const uint32_t bBase = sb + 30720u + (uint32_t)s * 10240u;
#pragma unroll
        for (int kk = 0; kk < 32; kk += 16) {
            uint32_t a[4][4];
#pragma unroll
            for (int mt = 0; mt < 4; ++mt) {
                const uint32_t addr = aBase +
                    (uint32_t)((m_off + mt * 16 + (lane & 15)) * 40 + kk + ((lane >> 4) & 1) * 8) * 2u;
                ldm_x4(a[mt][0], a[mt][1], a[mt][2], a[mt][3], addr);
            }
            uint32_t b[4][2];
#pragma unroll
            for (int nt2 = 0; nt2 < 2; ++nt2) {
                const uint32_t addr = bBase +
                    (uint32_t)((n_off + nt2 * 16 + (lane & 7) + ((lane >> 4) & 1) * 8) * 40 +
                               kk + ((lane >> 3) & 1) * 8) * 2u;
                uint32_t r0, r1, r2, r3;
                ldm_x4(r0, r1, r2, r3, addr);
                b[nt2 * 2][0] = r0;     b[nt2 * 2][1] = r1;
                b[nt2 * 2 + 1][0] = r2; b[nt2 * 2 + 1][1] = r3;
            }
#pragma unroll
            for (int mt = 0; mt < 4; ++mt)
#pragma unroll
                for (int nt = 0; nt < 4; ++nt)
                    mma16816(acc[mt][nt], a[mt][0], a[mt][1], a[mt][2], a[mt][3],
                             b[nt][0], b[nt][1]);
        }
        if (kt + 2 < 24) { LOAD_STAGE((kt + 2) % 3, kt + 2) } else { CP_COMMIT(); }
    }

    // epilogue: bias add, float2 stores
    const int tr = lane >> 2, tc = (lane & 3) * 2;
#pragma unroll
    for (int mt = 0; mt < 4; ++mt)
#pragma unroll
        for (int nt = 0; nt < 4; ++nt) {
            const int gr = row0 + m_off + mt * 16 + tr;
            const int gc = col0 + n_off + nt * 8 + tc;
            const float2 bb = *(const float2*)(bias + gc);
            float2 v0 = {acc[mt][nt][0] + bb.x, acc[mt][nt][1] + bb.y};
            float2 v1 = {acc[mt][nt][2] + bb.x, acc[mt][nt][3] + bb.y};
            *(float2*)&g_pre[(size_t)gr * D_SAE + gc] = v0;
            *(float2*)&g_pre[(size_t)(gr + 8) * D_SAE + gc] = v1;
        }
}

// ======================================================================
// top-128 per row of approx pre (histogram radix select; superset only)
// ======================================================================
#define TK_CAP 3072
__global__ __launch_bounds__(256) void topk128() {
    __shared__ unsigned int hist[4096];
    __shared__ unsigned long long cand[TK_CAP];
    __shared__ unsigned int chunkSum[16];
    __shared__ int s_bin;
    __shared__ unsigned int s_cntHi, s_cntCand;

    const int row = blockIdx.x, tid = threadIdx.x;
    const float* rp = g_pre + (size_t)row * D_SAE;

    for (int i = tid; i < 4096; i += 256) hist[i] = 0;
    if (tid == 0) { s_cntHi = 0; s_cntCand = 0; }
    __syncthreads();

    for (int i = tid; i < D_SAE / 4; i += 256) {
        float4 v = *(const float4*)(rp + i * 4);
        atomicAdd(&hist[fkey(v.x) >> 20], 1u);
        atomicAdd(&hist[fkey(v.y) >> 20], 1u);
        atomicAdd(&hist[fkey(v.z) >> 20], 1u);
        atomicAdd(&hist[fkey(v.w) >> 20], 1u);
    }
    __syncthreads();

    if (tid < 16) {
        unsigned int s = 0;
        for (int j = 0; j < 256; ++j) s += hist[tid * 256 + j];
        chunkSum[tid] = s;
    }
    __syncthreads();
    if (tid == 0) {
        unsigned int cum = 0; int cb;
        for (cb = 15; cb > 0; --cb) {
            if (cum + chunkSum[cb] >= 128u) break;
            cum += chunkSum[cb];
        }
        int bin;
        for (bin = cb * 256 + 255; bin > cb * 256; --bin) {
            if (cum + hist[bin] >= 128u) break;
            cum += hist[bin];
        }
        s_bin = bin;
    }
    __syncthreads();

    const int tb = s_bin;
    for (int i = tid; i < D_SAE / 4; i += 256) {
        float4 v = *(const float4*)(rp + i * 4);
        float vv[4] = {v.x, v.y, v.z, v.w};
#pragma unroll
        for (int c = 0; c < 4; ++c) {
            const unsigned int k = fkey(vv[c]);
            const int bin = (int)(k >> 20);
            const int idx = i * 4 + c;
            if (bin > tb) {
                unsigned int p = atomicAdd(&s_cntHi, 1u);
                g_topidx[row * 128 + p] = idx;
                g_topval[row * 128 + p] = vv[c];
            } else if (bin == tb) {
                unsigned int q = atomicAdd(&s_cntCand, 1u);
                if (q < TK_CAP) cand[q] = makeComp(vv[c], idx);
            }
        }
    }
    __syncthreads();

    const int need = 128 - (int)s_cntHi;
    const int nc = min((int)s_cntCand, TK_CAP);
    for (int c = tid; c < nc; c += 256) {
        const unsigned long long me = cand[c];
        int r = 0;
        for (int j = 0; j < nc; ++j) r += (cand[j] > me);
        if (r < need) {
            const int pos = (int)s_cntHi + r;
            g_topidx[row * 128 + pos] = (int)(0xFFFFFFFFu - (unsigned int)me);
            g_topval[row * 128 + pos] = keyToFloat((unsigned int)(me >> 32));
        }
    }
}

// ======================================================================
// Scan: approx rank -> exact recompute of boundary band -> re-rank ->
// exact recompute of 64 winners. z values exact; selections exact.
// ======================================================================
#define MARGIN 0.008f
__global__ __launch_bounds__(256) void scan_kernel(const float* __restrict__ X,
                                                   const float* __restrict__ gate_raw,
                                                   const float* __restrict__ b_enc) {
    __shared__ unsigned int bitmap[D_SAE / 32];   // 384 words
    __shared__ int prevIdx[KTOP];
    __shared__ float prevVal[KTOP];
    __shared__ unsigned long long cand[208];
    __shared__ float candAdd[208];
    __shared__ int tmpIdx[KTOP];
    __shared__ float tmpVal[KTOP];
    __shared__ float tmpAdd[KTOP];
    __shared__ float xrow[D_IN];
    __shared__ int flagList[96];
    __shared__ int s_ncand, s_nflag;
    __shared__ float s_v64;

    const int b = blockIdx.x, tid = threadIdx.x, lane = tid & 31, w = tid >> 5;
    for (int i = tid; i < D_SAE / 32; i += 256) bitmap[i] = 0;
    int nprev = 0;
    __syncthreads();

    for (int t = 0; t < T_LEN; ++t) {
        const int row = b * T_LEN + t;
        for (int i = tid; i < D_IN; i += 256) xrow[i] = X[(size_t)row * D_IN + i];
        if (tid == 0) { s_ncand = nprev; s_nflag = 0; }
        __syncthreads();

        if (tid < nprev) {
            const int idx = prevIdx[tid];
            const float gate = 1.0f / (1.0f + expf(-gate_raw[idx]));
            const float add = gate * prevVal[tid];
            cand[tid] = makeComp(add + g_pre[(size_t)row * D_SAE + idx], idx);
            candAdd[tid] = add;
        }
        if (tid < 128) {
            const int idx = g_topidx[row * 128 + tid];
            if (!((bitmap[idx >> 5] >> (idx & 31)) & 1u)) {
                const int p = atomicAdd(&s_ncand, 1);
                cand[p] = makeComp(g_topval[row * 128 + tid], idx);
                candAdd[p] = 0.0f;
            }
        }
        __syncthreads();

        const int n = s_ncand;
        // pass 1: approx rank, find 64th value
        if (tid < n) {
            const unsigned long long me = cand[tid];
            int r = 0;
            for (int j = 0; j < n; ++j) r += (cand[j] > me);
            if (r == 63) s_v64 = keyToFloat((unsigned int)(me >> 32));
        }
        __syncthreads();
        // flag boundary band
        if (tid < n) {
            const float v = keyToFloat((unsigned int)(cand[tid] >> 32));
            if (fabsf(v - s_v64) <= MARGIN) {
                const int p = atomicAdd(&s_nflag, 1);
                if (p < 96) flagList[p] = tid;
            }
        }
        __syncthreads();
        // exact recompute of flagged candidates (one warp each)
        const int nf = min(s_nflag, 96);
        for (int f = w; f < nf; f += 8) {
            const int ci = flagList[f];
            const int idx = (int)(0xFFFFFFFFu - (unsigned int)cand[ci]);
            const float* wt = g_WT + (size_t)idx * D_IN;
            float sacc = 0.f;
            for (int k = lane; k < D_IN; k += 32) sacc += xrow[k] * wt[k];
#pragma unroll
            for (int o = 16; o; o >>= 1) sacc += __shfl_xor_sync(0xFFFFFFFFu, sacc, o);
            if (lane == 0) cand[ci] = makeComp(candAdd[ci] + sacc + b_enc[idx], idx);
        }
        __syncthreads();
        // pass 2: final rank
        if (tid < n) {
            const unsigned long long me = cand[tid];
            int r = 0;
            for (int j = 0; j < n; ++j) r += (cand[j] > me);
            if (r < KTOP) {
                tmpIdx[r] = (int)(0xFFFFFFFFu - (unsigned int)me);
                tmpAdd[r] = candAdd[tid];
            }
        }
        __syncthreads();
        // exact recompute of all 64 winners (z exact)
        for (int s2 = w; s2 < KTOP; s2 += 8) {
            const int idx = tmpIdx[s2];
            const float* wt = g_WT + (size_t)idx * D_IN;
            float sacc = 0.f;
            for (int k = lane; k < D_IN; k += 32) sacc += xrow[k] * wt[k];
#pragma unroll
            for (int o = 16; o; o >>= 1) sacc += __shfl_xor_sync(0xFFFFFFFFu, sacc, o);
            if (lane == 0) tmpVal[s2] = fmaxf(tmpAdd[s2] + sacc + b_enc[idx], 0.0f);
        }
        __syncthreads();

        if (tid < nprev) atomicAnd(&bitmap[prevIdx[tid] >> 5], ~(1u << (prevIdx[tid] & 31)));
        __syncthreads();
        if (tid < KTOP) {
            const int idx = tmpIdx[tid];
            const float v = tmpVal[tid];
            prevIdx[tid] = idx; prevVal[tid] = v;
            atomicOr(&bitmap[idx >> 5], 1u << (idx & 31));
            g_zidx[row * KTOP + tid] = idx;
            g_zval[row * KTOP + tid] = v;
        }
        nprev = KTOP;
        __syncthreads();
    }
}

// ======================================================================
// Sparse decode + per-row squared error. (xhat only 4B-aligned)
// ======================================================================
__global__ __launch_bounds__(192) void decode_kernel(const float* __restrict__ X,
                                                     const float* __restrict__ Wd,
                                                     const float* __restrict__ b_dec,
                                                     float* __restrict__ xhat) {
    __shared__ int sIdx[KTOP];
    __shared__ float sVal[KTOP];
    __shared__ float red[192];
    const int row = blockIdx.x, tid = threadIdx.x;
    if (tid < KTOP) {
        sIdx[tid] = g_zidx[row * KTOP + tid];
        sVal[tid] = g_zval[row * KTOP + tid];
    }
    __syncthreads();

    float4 acc = *(const float4*)(b_dec + tid * 4);
#pragma unroll 4
    for (int k = 0; k < KTOP; ++k) {
        const float v = sVal[k];
        const float4 wv = *(const float4*)(Wd + (size_t)sIdx[k] * D_IN + tid * 4);
        acc.x += v * wv.x; acc.y += v * wv.y; acc.z += v * wv.z; acc.w += v * wv.w;
    }
    float* op = xhat + (size_t)row * D_IN + tid * 4;
    op[0] = acc.x; op[1] = acc.y; op[2] = acc.z; op[3] = acc.w;

    const float4 xv = *(const float4*)(X + (size_t)row * D_IN + tid * 4);
    const float dx = acc.x - xv.x, dy = acc.y - xv.y, dz = acc.z - xv.z, dw = acc.w - xv.w;
    red[tid] = dx * dx + dy * dy + dz * dz + dw * dw;
    __syncthreads();
    for (int s = 96; s >= 6; s >>= 1) {
        if (tid < s) red[tid] += red[tid + s];
        __syncthreads();
    }
    if (tid == 0) {
        float total = 0.f;
        for (int i = 0; i < 6; ++i) total += red[i];
        g_rowloss[row] = total;
    }
}

// ======================================================================
// Finalization
// ======================================================================
__global__ void zero_zlast(float* __restrict__ z) {
    const int i = blockIdx.x * blockDim.x + threadIdx.x;
    if (i < BATCH * D_SAE) z[i] = 0.0f;
}
__global__ void scatter_zlast(float* __restrict__ z) {
    const int gid = blockIdx.x * blockDim.x + threadIdx.x;
    if (gid < BATCH * KTOP) {
        const int b = gid >> 6, k = gid & 63;
        const int row = b * T_LEN + (T_LEN - 1);
        z[(size_t)b * D_SAE + g_zidx[row * KTOP + k]] = g_zval[row * KTOP + k];
    }
}
__global__ __launch_bounds__(1024) void loss_kernel(float* __restrict__ out) {
    __shared__ float red[1024];
    const int tid = threadIdx.x;
    red[tid] = g_rowloss[tid] + g_rowloss[tid + 1024];
    __syncthreads();
    for (int s = 512; s > 0; s >>= 1) {
        if (tid < s) red[tid] += red[tid + s];
        __syncthreads();
    }
    if (tid == 0) out[0] = red[0] / (float)NROWS;
}

// ======================================================================
extern "C" void kernel_launch(void* const* d_in, const int* in_sizes, int n_in,
                              void* d_out, int out_size) {
    const float* x        = (const float*)d_in[0];
    const float* W_enc    = (const float*)d_in[1];
    const float* W_dec    = (const float*)d_in[2];
    const float* b_enc    = (const float*)d_in[3];
    const float* b_dec    = (const float*)d_in[4];
    const float* gate_raw = (const float*)d_in[5];

    float* out       = (float*)d_out;
    float* out_loss  = out;
    float* out_xhat  = out + 1;
    float* out_zlast = out + 1 + (size_t)NROWS * D_IN;

    cudaFuncSetAttribute(gemm_mma, cudaFuncAttributeMaxDynamicSharedMemorySize, GSMEM);

    conv_A<<<(NROWS * D_IN) / 256, 256>>>(x);
    conv_WT<<<dim3(D_SAE / 64, D_IN / 32), 256>>>(W_enc);
    gemm_mma<<<dim3(D_SAE / 128, NROWS / 128), 256, GSMEM>>>(b_enc);
    topk128<<<NROWS, 256>>>();
    scan_kernel<<<BATCH, 256>>>(x, gate_raw, b_enc);
    decode_kernel<<<NROWS, 192>>>(x, W_dec, b_dec, out_xhat);
    zero_zlast<<<(BATCH * D_SAE + 255) / 256, 256>>>(out_zlast);
    scatter_zlast<<<(BATCH * KTOP + 255) / 256, 256>>>(out_zlast);
    loss_kernel<<<1, 1024>>>(out_loss);
}